// round 16
// baseline (speedup 1.0000x reference)
#include <cuda_runtime.h>
#include <cuda_fp16.h>
#include <math.h>

// LocalSTD: out = sqrt( G*x^2 - (G*x)^2 + 1e-6 ), 11x11 Gaussian sigma=1,
// separable, 7 taps renormalized.
// WARP-SPECIALIZED STRIP KERNEL:
//   warps 0-3 (producers): stream a 64-row strip ONCE (rolling 8-slot packed
//     vertical scatter, fma.rn.f32x2, independent accumulators), emit half2
//     (m, var) rows into double-buffered smem.
//   warps 4-7 (consumers): R12 read-once horizontal scatter + epilogue,
//     one 8-row chunk behind, one barrier per chunk.
// Vertical halo redundancy drops 1.75x -> 1.094x; phase latencies overlap
// across warps.

#define Wd 256
#define Hd 256
#define SH 64            // strip height (output rows per block)
#define NCHUNK 8         // 8 chunks of 8 rows
#define HALO 3           // 7 taps
#define PD 4             // producer prefetch depth
#define NT 256           // 128 producers + 128 consumers
#define RS 332           // u32 (half2) per smem row: 16 segs * 20 + edge

// 7-tap Gaussian (sigma=1) renormalized: pdf(k)/0.99972937, k=-3..3
#define GW2 4.4330480e-03f
#define GW3 5.4005582e-02f
#define GW4 2.4203623e-01f
#define GW5 3.9905027e-01f

typedef unsigned long long u64;
typedef unsigned int u32;

__device__ __forceinline__ u64 pack2(float lo, float hi) {
    u64 r;
    asm("mov.b64 %0, {%1, %2};" : "=l"(r) : "f"(lo), "f"(hi));
    return r;
}
__device__ __forceinline__ void unpack2(u64 v, float& lo, float& hi) {
    asm("mov.b64 {%0, %1}, %2;" : "=f"(lo), "=f"(hi) : "l"(v));
}
__device__ __forceinline__ u64 fma2(u64 a, u64 b, u64 c) {
    u64 d;
    asm("fma.rn.f32x2 %0, %1, %2, %3;" : "=l"(d) : "l"(a), "l"(b), "l"(c));
    return d;
}
__device__ __forceinline__ float fsqrt_approx(float a) {
    float r;
    asm("sqrt.approx.f32 %0, %1;" : "=f"(r) : "f"(a));
    return r;
}
__device__ __forceinline__ u32 h2bits(float m, float v) {
    const __half2 h = __floats2half2_rn(m, v);
    return *reinterpret_cast<const u32*>(&h);
}
// half2 bits -> packed fp32 (m, e=v+m^2)
__device__ __forceinline__ u64 prep(u32 bits) {
    const __half2 h = *reinterpret_cast<const __half2*>(&bits);
    const float2 f = __half22float2(h);
    const float e = fmaf(f.x, f.x, f.y);
    return pack2(f.x, e);
}

// weight index with symmetry: tap j (0..6) -> wq[j<4 ? j : 6-j]
#define WQ(J) (wq[(J) < 4 ? (J) : 6 - (J)])

// producer: process one streamed input row. QV = static phase value of q
// (q mod 8 and q mod 4 both match QV). NEGG: guard o=q-k >= 0 (prologue only).
#define PSTEP(QV, NEGG)                                                   \
    {                                                                     \
        const float2 v = pf[(QV) & 3];                                    \
        if (SAFE) {                                                       \
            pf[(QV) & 3] = (prin >= 0 && prin < Hd)                       \
                         ? *(const float2*)pgp : make_float2(0.f, 0.f);   \
        } else {                                                          \
            pf[(QV) & 3] = *(const float2*)pgp;                           \
        }                                                                 \
        pgp += Wd; ++prin;                                                \
        const u64 p0 = pack2(v.x, v.x * v.x);                             \
        const u64 p1 = pack2(v.y, v.y * v.y);                             \
        _Pragma("unroll")                                                 \
        for (int k = 0; k < 7; ++k)                                       \
            if (!(NEGG) || (QV) - k >= 0) {                               \
                const int sl = ((QV) - k) & 7;                            \
                acc0[sl] = fma2(WQ(k), p0, acc0[sl]);                     \
                acc1[sl] = fma2(WQ(k), p1, acc1[sl]);                     \
            }                                                             \
    }

// consumer scatter: window position k (0..21) into 16 packed accumulators
#define SCAT(K, BITS)                                                     \
    {                                                                     \
        const u64 _v = prep(BITS);                                        \
        _Pragma("unroll")                                                 \
        for (int j = 0; j < 16; ++j)                                      \
            if (j >= (K) - 6 && j <= (K))                                 \
                acc2[j] = fma2(WQ((K) - j), _v, acc2[j]);                 \
    }

template<bool SAFE>
__device__ __forceinline__ void run_block(const float* __restrict__ xp,
                                          float* __restrict__ op,
                                          u32 (*buf)[8][RS],
                                          const int rb, const int t) {
    u64 wq[4];
    wq[0] = pack2(GW2, GW2);
    wq[1] = pack2(GW3, GW3);
    wq[2] = pack2(GW4, GW4);
    wq[3] = pack2(GW5, GW5);

    if (t < 128) {
        // ================= PRODUCER (warps 0-3) =================
        const int c0 = 2 * t;
        const int ph = 8 + 20 * (t >> 3) + (c0 & 15);   // segment slot

        u64 acc0[8], acc1[8];
#pragma unroll
        for (int i = 0; i < 8; ++i) { acc0[i] = 0ull; acc1[i] = 0ull; }

        // prime prefetch ring with q = 0..PD-1 (input row rb-3+q)
        float2 pf[PD];
#pragma unroll
        for (int p = 0; p < PD; ++p) {
            const int rin = rb - HALO + p;
            if (SAFE) {
                pf[p] = (rin >= 0 && rin < Hd)
                      ? *(const float2*)(xp + (size_t)rin * Wd + c0)
                      : make_float2(0.f, 0.f);
            } else {
                pf[p] = *(const float2*)(xp + (size_t)rin * Wd + c0);
            }
        }
        const float* pgp = xp + (size_t)(rb - HALO + PD) * Wd + c0;
        int prin = rb - HALO + PD;

        // prologue: q = 0..5 (no emissions; compile-time o>=0 pruning)
        PSTEP(0, true) PSTEP(1, true) PSTEP(2, true)
        PSTEP(3, true) PSTEP(4, true) PSTEP(5, true)

        // main: chunk c streams q = 8c+6 .. 8c+13, emits outputs 8c..8c+7
        for (int c = 0; c <= NCHUNK; ++c) {
            if (c < NCHUNK) {
                u32 (*sb)[RS] = buf[c & 1];
#pragma unroll
                for (int qq = 0; qq < 8; ++qq) {
                    switch (qq) {   // static phase per position
                        case 0: PSTEP(6,  false) break;
                        case 1: PSTEP(7,  false) break;
                        case 2: PSTEP(8,  false) break;
                        case 3: PSTEP(9,  false) break;
                        case 4: PSTEP(10, false) break;
                        case 5: PSTEP(11, false) break;
                        case 6: PSTEP(12, false) break;
                        case 7: PSTEP(13, false) break;
                    }
                    // emit completed output row (slot qq), reset slot
                    float m0, e0, m1, e1;
                    unpack2(acc0[qq], m0, e0);
                    unpack2(acc1[qq], m1, e1);
                    uint2 w2;
                    w2.x = h2bits(m0, fmaf(-m0, m0, e0));
                    w2.y = h2bits(m1, fmaf(-m1, m1, e1));
                    *(uint2*)&sb[qq][ph] = w2;
                    acc0[qq] = 0ull; acc1[qq] = 0ull;
                }
            }
            __syncthreads();
        }
    } else {
        // ================= CONSUMER (warps 4-7) =================
        const int ct = t - 128;
        const int r = ct >> 4;          // chunk-local row 0..7
        const int s = ct & 15;          // 16-col segment

        // zero the edge-halo slots of both buffers once
        if (ct < 16) {
            const int bs = ct >> 3, ri = ct & 7;
            buf[bs][ri][1] = 0u;   buf[bs][ri][2] = 0u;   buf[bs][ri][3] = 0u;
            buf[bs][ri][328] = 0u; buf[bs][ri][329] = 0u; buf[bs][ri][330] = 0u;
        }

        for (int c = 0; c <= NCHUNK; ++c) {
            if (c > 0) {
                const int k = c - 1;                 // chunk being consumed
                const u32* row = &buf[k & 1][r][20 * s];

                u64 acc2[16];
#pragma unroll
                for (int j = 0; j < 16; ++j) acc2[j] = 0ull;

                {   // left halo: idx 0(dead),1,2,3 -> cols 16s-3..16s-1
                    const uint4 p = *(const uint4*)(row + 0);
                    SCAT(0, p.y); SCAT(1, p.z); SCAT(2, p.w);
                }
#pragma unroll
                for (int q = 0; q < 4; ++q) {        // own cols 16s..16s+15
                    const uint4 p = *(const uint4*)(row + 8 + 4 * q);
                    SCAT(3 + 4 * q, p.x);
                    SCAT(4 + 4 * q, p.y);
                    SCAT(5 + 4 * q, p.z);
                    SCAT(6 + 4 * q, p.w);
                }
                {   // right halo: idx 28,29,30,31(dead) -> cols 16s+16..18
                    const uint4 p = *(const uint4*)(row + 28);
                    SCAT(19, p.x); SCAT(20, p.y); SCAT(21, p.z);
                }

                float* orow = op + (size_t)(rb + 8 * k + r) * Wd + 16 * s;
#pragma unroll
                for (int g = 0; g < 4; ++g) {
                    float o[4];
#pragma unroll
                    for (int q = 0; q < 4; ++q) {
                        float m, e;
                        unpack2(acc2[4 * g + q], m, e);
                        o[q] = fsqrt_approx(fmaf(-m, m, e) + 1e-6f);
                    }
                    *(float4*)(orow + 4 * g) = make_float4(o[0], o[1], o[2], o[3]);
                }
            }
            __syncthreads();
        }
    }
}

__global__ void __launch_bounds__(NT, 4)
local_std_kernel(const float* __restrict__ x, float* __restrict__ out) {
    __shared__ __align__(16) u32 buf[2][8][RS];   // double-buffered chunks

    const int t = threadIdx.x;
    const int plane = blockIdx.y;              // 0..1023
    const int rb = blockIdx.x * SH;            // first output row of strip
    const float* __restrict__ xp = x + (size_t)plane * (Wd * Hd);
    float* __restrict__ op = out + (size_t)plane * (Wd * Hd);

    if (rb >= HALO && rb + SH + HALO <= Hd) {
        run_block<false>(xp, op, buf, rb, t);
    } else {
        run_block<true>(xp, op, buf, rb, t);
    }
}

extern "C" void kernel_launch(void* const* d_in, const int* in_sizes, int n_in,
                              void* d_out, int out_size) {
    const float* x = (const float*)d_in[0];
    float* out = (float*)d_out;

    const int planes = in_sizes[0] / (Wd * Hd);   // 16*64 = 1024
    dim3 grid(Hd / SH, planes);                    // (4, 1024)
    local_std_kernel<<<grid, NT>>>(x, out);
}

// round 17
// speedup vs baseline: 1.1224x; 1.1224x over previous
#include <cuda_runtime.h>
#include <cuda_fp16.h>
#include <math.h>

// LocalSTD: out = sqrt( G*x^2 - (G*x)^2 + 1e-6 ), 11x11 Gaussian sigma=1,
// separable, 7 taps renormalized.
// R12 backbone with ROLLING-EMISSION phase 1 at CH=16:
//   phase 1 streams 22 rows/block; each row scatters (packed fma.rn.f32x2)
//   into <=7 of 8 rolling slot-accumulators (independent, static indices);
//   completed output rows are emitted as half2 (m, var) to smem immediately,
//   freeing the slot -> CH=16 vertical state in 32 regs (vs 64 for direct).
//   Vertical halo amplification 1.75x -> 1.375x; half the blocks.
// Exchange: fp16 (m, v) cancellation-safe, segment-padded layout.
// Phase 2: read-once horizontal scatter (row x 16-col segment), e=v+m^2
//   rebuilt in fp32, packed fma2; 2 tasks per thread. One barrier total.

#define Wd 256
#define Hd 256
#define CH 16            // output rows per block
#define HALO 3           // 7 taps
#define NR (CH + 2*HALO) // 22 input rows streamed
#define PD 4             // global-load prefetch depth
#define NT 128           // threads (2 columns each in phase 1)
#define RS 332           // u32 (half2) per smem row: 16 segs * 20 + edge

// 7-tap Gaussian (sigma=1) renormalized: pdf(k)/0.99972937, k=-3..3
#define GW2 4.4330480e-03f
#define GW3 5.4005582e-02f
#define GW4 2.4203623e-01f
#define GW5 3.9905027e-01f

typedef unsigned long long u64;
typedef unsigned int u32;

__device__ __forceinline__ u64 pack2(float lo, float hi) {
    u64 r;
    asm("mov.b64 %0, {%1, %2};" : "=l"(r) : "f"(lo), "f"(hi));
    return r;
}
__device__ __forceinline__ void unpack2(u64 v, float& lo, float& hi) {
    asm("mov.b64 {%0, %1}, %2;" : "=f"(lo), "=f"(hi) : "l"(v));
}
__device__ __forceinline__ u64 fma2(u64 a, u64 b, u64 c) {
    u64 d;
    asm("fma.rn.f32x2 %0, %1, %2, %3;" : "=l"(d) : "l"(a), "l"(b), "l"(c));
    return d;
}
__device__ __forceinline__ float fsqrt_approx(float a) {
    float r;
    asm("sqrt.approx.f32 %0, %1;" : "=f"(r) : "f"(a));
    return r;
}
__device__ __forceinline__ u32 h2bits(float m, float v) {
    const __half2 h = __floats2half2_rn(m, v);
    return *reinterpret_cast<const u32*>(&h);
}
// half2 bits -> packed fp32 (m, e=v+m^2)
__device__ __forceinline__ u64 prep(u32 bits) {
    const __half2 h = *reinterpret_cast<const __half2*>(&bits);
    const float2 f = __half22float2(h);
    const float e = fmaf(f.x, f.x, f.y);
    return pack2(f.x, e);
}

// weight index with symmetry: tap j (0..6) -> wq[j<4 ? j : 6-j]
#define WQ(J) (wq[(J) < 4 ? (J) : 6 - (J)])

// consumer scatter: window position k (0..21) into 16 packed accumulators
#define SCAT(K, BITS)                                                     \
    {                                                                     \
        const u64 _v = prep(BITS);                                        \
        _Pragma("unroll")                                                 \
        for (int j = 0; j < 16; ++j)                                      \
            if (j >= (K) - 6 && j <= (K))                                 \
                acc2[j] = fma2(WQ((K) - j), _v, acc2[j]);                 \
    }

template<bool SAFE>
__device__ __forceinline__ void body(const float* __restrict__ xp,
                                     float* __restrict__ op,
                                     u32 (*sh)[RS],
                                     const int rb, const int t) {
    const int c0 = 2 * t;
    const int ph = 8 + 20 * (t >> 3) + (c0 & 15);   // segment slot (aligned)

    u64 wq[4];
    wq[0] = pack2(GW2, GW2);
    wq[1] = pack2(GW3, GW3);
    wq[2] = pack2(GW4, GW4);
    wq[3] = pack2(GW5, GW5);

    // ---- phase 1: stream NR rows; 8 rolling slot-accumulators ----
    u64 acc0[8], acc1[8];
#pragma unroll
    for (int i = 0; i < 8; ++i) { acc0[i] = 0ull; acc1[i] = 0ull; }

    float2 pf[PD];
#pragma unroll
    for (int p = 0; p < PD; ++p) {
        const int rin = rb - HALO + p;
        if (SAFE) {
            pf[p] = (rin >= 0 && rin < Hd)
                  ? *(const float2*)(xp + (size_t)rin * Wd + c0)
                  : make_float2(0.f, 0.f);
        } else {
            pf[p] = *(const float2*)(xp + (size_t)rin * Wd + c0);
        }
    }

#pragma unroll
    for (int q = 0; q < NR; ++q) {           // q: stream index, all static
        const float2 v = pf[q & (PD - 1)];
        if (q + PD < NR) {
            const int rin = rb - HALO + q + PD;
            if (SAFE) {
                pf[q & (PD - 1)] = (rin >= 0 && rin < Hd)
                                 ? *(const float2*)(xp + (size_t)rin * Wd + c0)
                                 : make_float2(0.f, 0.f);
            } else {
                pf[q & (PD - 1)] = *(const float2*)(xp + (size_t)rin * Wd + c0);
            }
        }
        const u64 p0 = pack2(v.x, v.x * v.x);
        const u64 p1 = pack2(v.y, v.y * v.y);

        // tap k at stream q contributes to output o = q - k
#pragma unroll
        for (int k = 0; k < 7; ++k) {
            const int o = q - k;
            if (o >= 0 && o < CH) {
                const int sl = o & 7;
                acc0[sl] = fma2(WQ(k), p0, acc0[sl]);
                acc1[sl] = fma2(WQ(k), p1, acc1[sl]);
            }
        }

        // output o = q-6 is complete: emit half2 (m, var), recycle slot
        if (q >= 6) {
            const int o = q - 6;
            const int sl = o & 7;
            float m0, e0, m1, e1;
            unpack2(acc0[sl], m0, e0);
            unpack2(acc1[sl], m1, e1);
            uint2 w2;
            w2.x = h2bits(m0, fmaf(-m0, m0, e0));
            w2.y = h2bits(m1, fmaf(-m1, m1, e1));
            *(uint2*)&sh[o][ph] = w2;
            acc0[sl] = 0ull;
            acc1[sl] = 0ull;
        }
    }

    // edge zeros: cols -3..-1 and 256..258 for all CH rows
    if (t < CH) {
        sh[t][1] = 0u;   sh[t][2] = 0u;   sh[t][3] = 0u;
        sh[t][328] = 0u; sh[t][329] = 0u; sh[t][330] = 0u;
    }
    __syncthreads();

    // ---- phase 2: read-once scatter; 2 (row, segment) tasks per thread ----
#pragma unroll
    for (int task = 0; task < 2; ++task) {
        const int r = (t >> 4) + 8 * task;
        const int s = t & 15;
        const u32* row = &sh[r][20 * s];

        u64 acc2[16];
#pragma unroll
        for (int j = 0; j < 16; ++j) acc2[j] = 0ull;

        {   // left halo: uint4 idx 0(dead),1,2,3 -> cols 16s-3..16s-1
            const uint4 p = *(const uint4*)(row + 0);
            SCAT(0, p.y); SCAT(1, p.z); SCAT(2, p.w);
        }
#pragma unroll
        for (int q = 0; q < 4; ++q) {                  // own cols 16s..16s+15
            const uint4 p = *(const uint4*)(row + 8 + 4 * q);
            SCAT(3 + 4 * q, p.x);
            SCAT(4 + 4 * q, p.y);
            SCAT(5 + 4 * q, p.z);
            SCAT(6 + 4 * q, p.w);
        }
        {   // right halo: uint4 idx 28,29,30,31(dead) -> cols 16s+16..18
            const uint4 p = *(const uint4*)(row + 28);
            SCAT(19, p.x); SCAT(20, p.y); SCAT(21, p.z);
        }

        // epilogue: var -> std, 4x STG.128
        float* orow = op + (size_t)(rb + r) * Wd + 16 * s;
#pragma unroll
        for (int g = 0; g < 4; ++g) {
            float o[4];
#pragma unroll
            for (int q = 0; q < 4; ++q) {
                float m, e;
                unpack2(acc2[4 * g + q], m, e);
                o[q] = fsqrt_approx(fmaf(-m, m, e) + 1e-6f);
            }
            *(float4*)(orow + 4 * g) = make_float4(o[0], o[1], o[2], o[3]);
        }
    }
}

__global__ void __launch_bounds__(NT, 8)
local_std_kernel(const float* __restrict__ x, float* __restrict__ out) {
    __shared__ __align__(16) u32 sh[CH][RS];

    const int t = threadIdx.x;
    const int plane = blockIdx.y;              // 0..1023
    const int rb = blockIdx.x * CH;            // first output row of chunk
    const float* __restrict__ xp = x + (size_t)plane * (Wd * Hd);
    float* __restrict__ op = out + (size_t)plane * (Wd * Hd);

    if (rb >= HALO && rb + CH + HALO <= Hd) {
        body<false>(xp, op, sh, rb, t);
    } else {
        body<true>(xp, op, sh, rb, t);
    }
}

extern "C" void kernel_launch(void* const* d_in, const int* in_sizes, int n_in,
                              void* d_out, int out_size) {
    const float* x = (const float*)d_in[0];
    float* out = (float*)d_out;

    const int planes = in_sizes[0] / (Wd * Hd);   // 16*64 = 1024
    dim3 grid(Hd / CH, planes);                    // (16, 1024)
    local_std_kernel<<<grid, NT>>>(x, out);
}